// round 14
// baseline (speedup 1.0000x reference)
#include <cuda_runtime.h>
#include <cuda_fp16.h>
#include <cstdint>
#include <cstddef>

#define N    8192
#define FIN  512
#define FOUT 256
#define JT     64                 // j per chunk
#define SPLITS 2
#define JHALF  (N / SPLITS)       // 4096
#define NCHUNK (JHALF / JT)       // 64
#define ITILE  64                 // i rows per CTA

// ---------------- scratch (no cudaMalloc allowed) ----------------
__device__ __half g_hT[FOUT * N];             // 4 MB  h^T fp16  [f][i]
__device__ float  g_Wa1[FIN], g_Wa2[FIN];
__device__ float  g_t[N];                     // f2 * log2(e)
__device__ float  g_u[N];                     // f1 * log2(e)
__device__ int    g_maxbits;                  // max of (t + 64) as fp32 bits (positive)
__device__ float  g_pnum[256 * 64 * 256];     // partial numerators (16.8 MB)
__device__ float  g_pz[256 * 64];             // partial Z

#define L2E 1.4426950408889634f

typedef unsigned long long ull;

// ---------------- PTX helpers (baseline sm_80+, legal at .target sm_100) ----
__device__ __forceinline__ uint32_t smem_u32(const void* p) {
    uint32_t a;
    asm("{ .reg .u64 t; cvta.to.shared.u64 t, %1; cvt.u32.u64 %0, t; }" : "=r"(a) : "l"(p));
    return a;
}
#define CP_ASYNC16(dst, src) \
    asm volatile("cp.async.cg.shared.global [%0], [%1], 16;" :: "r"((uint32_t)(dst)), "l"(src) : "memory")
#define CP_COMMIT() asm volatile("cp.async.commit_group;" ::: "memory")
#define CP_WAIT0()  asm volatile("cp.async.wait_group 0;" ::: "memory")

__device__ __forceinline__ void ldsm4(uint32_t* r, uint32_t addr) {
    asm volatile("ldmatrix.sync.aligned.m8n8.x4.shared.b16 {%0,%1,%2,%3}, [%4];"
        : "=r"(r[0]), "=r"(r[1]), "=r"(r[2]), "=r"(r[3]) : "r"(addr));
}
__device__ __forceinline__ void mmaf16(float* d, const uint32_t* a, uint32_t b0, uint32_t b1) {
    asm volatile("mma.sync.aligned.m16n8k16.row.col.f32.f16.f16.f32 "
        "{%0,%1,%2,%3}, {%4,%5,%6,%7}, {%8,%9}, {%0,%1,%2,%3};"
        : "+f"(d[0]), "+f"(d[1]), "+f"(d[2]), "+f"(d[3])
        : "r"(a[0]), "r"(a[1]), "r"(a[2]), "r"(a[3]), "r"(b0), "r"(b1));
}
__device__ __forceinline__ float ex2(float x) {
    float r; asm("ex2.approx.f32 %0, %1;" : "=f"(r) : "f"(x)); return r;
}

__device__ __forceinline__ ull pk2(float lo, float hi) {
    ull r; asm("mov.b64 %0, {%1,%2};" : "=l"(r) : "f"(lo), "f"(hi)); return r;
}
__device__ __forceinline__ void upk2(ull v, float& lo, float& hi) {
    asm("mov.b64 {%0,%1}, %2;" : "=f"(lo), "=f"(hi) : "l"(v));
}
__device__ __forceinline__ ull fma2(ull a, ull b, ull c) {
    ull d; asm("fma.rn.f32x2 %0, %1, %2, %3;" : "=l"(d) : "l"(a), "l"(b), "l"(c)); return d;
}
__device__ __forceinline__ uint32_t sw128(uint32_t off) { return off ^ ((off >> 3) & 0x70); }

// ---------------------------------------------------------------------------
// Kernel 1: Wa1 = W @ a1, Wa2 = W @ a2 (+ init global max)
// ---------------------------------------------------------------------------
__global__ void k_wa(const float* __restrict__ W,
                     const float* __restrict__ a1,
                     const float* __restrict__ a2) {
    __shared__ float a1s[FOUT], a2s[FOUT];
    int tid = threadIdx.x;
    if (blockIdx.x == 0 && tid == 0) g_maxbits = 0;
    if (tid < FOUT) { a1s[tid] = a1[tid]; a2s[tid] = a2[tid]; }
    __syncthreads();
    int warp = tid >> 5, lane = tid & 31;
    int row = blockIdx.x * 8 + warp;
    const float* wr = W + (size_t)row * FOUT;
    float s1 = 0.f, s2 = 0.f;
    for (int c = lane; c < FOUT; c += 32) {
        float w = wr[c];
        s1 += w * a1s[c];
        s2 += w * a2s[c];
    }
    #pragma unroll
    for (int o = 16; o; o >>= 1) {
        s1 += __shfl_down_sync(0xFFFFFFFFu, s1, o);
        s2 += __shfl_down_sync(0xFFFFFFFFu, s2, o);
    }
    if (lane == 0) { g_Wa1[row] = s1; g_Wa2[row] = s2; }
}

// ---------------------------------------------------------------------------
// Kernel 2: exact fp32 logits f1,f2 -> log2-domain t,u + global max(t)
// ---------------------------------------------------------------------------
__global__ void k_f(const float* __restrict__ X) {
    __shared__ float wa1[FIN], wa2[FIN];
    int tid = threadIdx.x;
    for (int c = tid; c < FIN; c += 256) { wa1[c] = g_Wa1[c]; wa2[c] = g_Wa2[c]; }
    __syncthreads();
    int warp = tid >> 5, lane = tid & 31;
    int row = blockIdx.x * 8 + warp;
    const float* xr = X + (size_t)row * FIN;
    float s1 = 0.f, s2 = 0.f;
    for (int c = lane; c < FIN; c += 32) {
        float x = xr[c];
        s1 += x * wa1[c];
        s2 += x * wa2[c];
    }
    #pragma unroll
    for (int o = 16; o; o >>= 1) {
        s1 += __shfl_down_sync(0xFFFFFFFFu, s1, o);
        s2 += __shfl_down_sync(0xFFFFFFFFu, s2, o);
    }
    if (lane == 0) {
        float t = s2 * L2E;
        g_t[row] = t;
        g_u[row] = s1 * L2E;
        atomicMax(&g_maxbits, __float_as_int(t + 64.f));   // t+64 > 0 always
    }
}

// ---------------------------------------------------------------------------
// Kernel 3: h = X @ W (fp32), output TRANSPOSED as fp16: g_hT[f][i]
// ---------------------------------------------------------------------------
__global__ __launch_bounds__(256) void k_gemm(const float* __restrict__ X,
                                              const float* __restrict__ W) {
    __shared__ float Xs[64][17];
    __shared__ float Ws[16][64];
    __shared__ float Ts[64][65];
    int tid = threadIdx.x;
    int tx = tid & 15, ty = tid >> 4;
    int i0 = blockIdx.x * 64, n0 = blockIdx.y * 64;

    ull acc[4][2];
    #pragma unroll
    for (int qi = 0; qi < 4; qi++)
        for (int p = 0; p < 2; p++) acc[qi][p] = pk2(0.f, 0.f);

    for (int k0 = 0; k0 < FIN; k0 += 16) {
        {
            int c = tid & 15, r0 = tid >> 4;
            #pragma unroll
            for (int q = 0; q < 4; q++) {
                int r = r0 + 16 * q;
                Xs[r][c] = X[(size_t)(i0 + r) * FIN + k0 + c];
            }
        }
        {
            int c = tid & 63, r0 = tid >> 6;
            #pragma unroll
            for (int q = 0; q < 4; q++) {
                int r = r0 + 4 * q;
                Ws[r][c] = W[(size_t)(k0 + r) * FOUT + n0 + c];
            }
        }
        __syncthreads();
        #pragma unroll
        for (int k = 0; k < 16; k++) {
            float a_[4], b_[4];
            #pragma unroll
            for (int q = 0; q < 4; q++) a_[q] = Xs[ty * 4 + q][k];
            #pragma unroll
            for (int q = 0; q < 4; q++) b_[q] = Ws[k][tx * 4 + q];
            ull b20 = pk2(b_[0], b_[1]);
            ull b21 = pk2(b_[2], b_[3]);
            #pragma unroll
            for (int qi = 0; qi < 4; qi++) {
                ull av = pk2(a_[qi], a_[qi]);
                acc[qi][0] = fma2(av, b20, acc[qi][0]);
                acc[qi][1] = fma2(av, b21, acc[qi][1]);
            }
        }
        __syncthreads();
    }
    #pragma unroll
    for (int qi = 0; qi < 4; qi++) {
        float v0, v1, v2, v3;
        upk2(acc[qi][0], v0, v1);
        upk2(acc[qi][1], v2, v3);
        int il = ty * 4 + qi;
        Ts[tx * 4 + 0][il] = v0;
        Ts[tx * 4 + 1][il] = v1;
        Ts[tx * 4 + 2][il] = v2;
        Ts[tx * 4 + 3][il] = v3;
    }
    __syncthreads();
    {
        int fl = tid >> 2, ib = (tid & 3) * 16;
        __half hb[16];
        #pragma unroll
        for (int k = 0; k < 16; k++) hb[k] = __float2half(Ts[fl][ib + k]);
        size_t base = (size_t)(n0 + fl) * N + i0 + ib;
        *(uint4*)(g_hT + base)     = *(uint4*)&hb[0];
        *(uint4*)(g_hT + base + 8) = *(uint4*)&hb[8];
    }
}

// ---------------------------------------------------------------------------
// Kernel 4: masked-softmax aggregation via fp16 mma.sync, SINGLE chain.
// Log-domain weight gen (R13) + BATCHED ldsm inner loop (R14): per kstep,
// all 6 ldsm4 (2 A + 4 B) issue up front into register arrays, then 16 mma
// run with no smem dependency inside the chain.
// grid = 256: bx = split*128 + i_tile. CTA: 64 i x 256 f, JT=64, occ 2.
// ---------------------------------------------------------------------------
#define STAGE 40960
#define OFF_A(s) ((s) * STAGE)
#define OFF_B(s) ((s) * STAGE + 8192)
#define SMEM_ATTN (2 * STAGE)   // 81920

__global__ __launch_bounds__(256, 2) void k_attn(const int* __restrict__ adj) {
    extern __shared__ char smem[];
    const uint32_t sb = smem_u32(smem);
    const int tid = threadIdx.x;
    const int bx = blockIdx.x;
    const int i_tile = bx & 127, split = bx >> 7;
    const int i0 = i_tile * ITILE;
    const int jbase = split * JHALF;

    const int warp = tid >> 5, lane = tid & 31;
    const int mw = warp >> 2;          // m-warp: rows [mw*32, mw*32+32)
    const int fw = warp & 3;           // f-warp: cols [fw*64, fw*64+64)
    const int gr = lane >> 3, lr = lane & 7;
    const int a_rbase = mw * 32 + lr + (gr & 1) * 8;
    const int a_koff = (gr >> 1) * 8;
    const int b_roff = fw * 64 + lr + (gr >> 1) * 8;
    const int b_koff = (gr & 1) * 8;

    // weight-gen geometry: 64 x 64 tile, thread -> row tid>>2, 16 j
    const int il = tid >> 2;
    const int jb = (tid & 3) * 16;
    const float u = g_u[i0 + il];
    float kk;
    {
        float T = __int_as_float(g_maxbits) - 64.f;   // max_j t_j
        float smax = u + T;
        float b = (smax >= 0.f) ? smax : 0.2f * smax; // log2 of row max weight
        kk = 13.f - floorf(b);                        // scaled max in [2^13, 2^14)
    }
    const int* adjrow = adj + (size_t)(i0 + il) * N;
    float zacc = 0.f;

    float acc[64];
    #pragma unroll
    for (int q = 0; q < 64; q++) acc[q] = 0.f;

    auto fillB = [&](int s, int jglob) {
        const __half* src = g_hT + (size_t)tid * N + jglob;
        #pragma unroll
        for (int q = 0; q < 8; q++) {
            uint32_t sw = sw128(tid * 128 + q * 16);
            CP_ASYNC16(sb + OFF_B(s) + sw, src + q * 8);
        }
    };
    auto genA = [&](int s, const int4* am4, int jglob) {
        const int* am = (const int*)am4;
        const float4* tp = (const float4*)(g_t + jglob + jb);
        float tv[16];
        #pragma unroll
        for (int q = 0; q < 4; q++) {
            float4 t4 = tp[q];
            tv[q * 4 + 0] = t4.x;
            tv[q * 4 + 1] = t4.y;
            tv[q * 4 + 2] = t4.z;
            tv[q * 4 + 3] = t4.w;
        }
        uint32_t phv[8];
        #pragma unroll
        for (int p = 0; p < 8; p++) {
            float w[2];
            #pragma unroll
            for (int e = 0; e < 2; e++) {
                int jj = p * 2 + e;
                float s_ = tv[jj] + u;
                float ee = (s_ >= 0.f) ? s_ : 0.2f * s_;
                float wv = ex2(ee + kk);
                w[e] = am[jj] ? wv : 0.f;
            }
            __half2 hh = __floats2half2_rn(w[0], w[1]);
            zacc += __low2float(hh) + __high2float(hh);
            phv[p] = *(uint32_t*)&hh;
        }
        uint32_t sw0 = sw128((uint32_t)(il * 128 + jb * 2));
        uint32_t sw1 = sw128((uint32_t)(il * 128 + jb * 2 + 16));
        *(uint4*)(smem + OFF_A(s) + sw0) = make_uint4(phv[0], phv[1], phv[2], phv[3]);
        *(uint4*)(smem + OFF_A(s) + sw1) = make_uint4(phv[4], phv[5], phv[6], phv[7]);
    };

    // ---- prologue: chunk 0 into buffer 0 ----
    {
        int4 aR[4];
        const int4* ap = (const int4*)(adjrow + jbase + jb);
        aR[0] = ap[0]; aR[1] = ap[1]; aR[2] = ap[2]; aR[3] = ap[3];
        fillB(0, jbase);
        CP_COMMIT();
        genA(0, aR, jbase);
        CP_WAIT0();
        __syncthreads();
    }

    // ---- main loop: prefetch adj(c+1) -> MMA(c) -> genA(c+1) -> sync ----
    for (int c = 0; c < NCHUNK; c++) {
        const int s = c & 1;
        const bool more = (c + 1 < NCHUNK);
        int4 aR[4];
        int jn = jbase + (c + 1) * JT;
        if (more) {
            const int4* ap = (const int4*)(adjrow + jn + jb);
            aR[0] = ap[0]; aR[1] = ap[1]; aR[2] = ap[2]; aR[3] = ap[3];
            fillB(s ^ 1, jn);
            CP_COMMIT();
        }
        // ---- MMA over buffer s: per kstep, batch ALL ldsm then run mma dry ----
        #pragma unroll
        for (int k0 = 0; k0 < JT; k0 += 16) {
            uint32_t A0[4], A1[4], B[4][4];
            uint32_t ao0 = sw128((uint32_t)(a_rbase * 128 + (k0 + a_koff) * 2));
            uint32_t ao1 = sw128((uint32_t)((a_rbase + 16) * 128 + (k0 + a_koff) * 2));
            ldsm4(A0, sb + OFF_A(s) + ao0);
            ldsm4(A1, sb + OFF_A(s) + ao1);
            #pragma unroll
            for (int nb = 0; nb < 4; nb++) {
                uint32_t boff = sw128((uint32_t)((b_roff + nb * 16) * 128 + (k0 + b_koff) * 2));
                ldsm4(B[nb], sb + OFF_B(s) + boff);
            }
            #pragma unroll
            for (int nb = 0; nb < 4; nb++) {
                mmaf16(acc + nb * 8,          A0, B[nb][0], B[nb][1]);
                mmaf16(acc + nb * 8 + 4,      A0, B[nb][2], B[nb][3]);
                mmaf16(acc + 32 + nb * 8,     A1, B[nb][0], B[nb][1]);
                mmaf16(acc + 32 + nb * 8 + 4, A1, B[nb][2], B[nb][3]);
            }
        }
        if (more) {
            genA(s ^ 1, aR, jn);
            CP_WAIT0();
        }
        __syncthreads();
    }

    // ---- Z partial: reduce across the 4 threads sharing row il ----
    zacc += __shfl_xor_sync(0xFFFFFFFFu, zacc, 1);
    zacc += __shfl_xor_sync(0xFFFFFFFFu, zacc, 2);
    if ((tid & 3) == 0) g_pz[bx * ITILE + il] = zacc;

    // ---- accumulators -> gmem partial numerators ----
    {
        const int qr = lane >> 2, qc = lane & 3;
        #pragma unroll
        for (int mt = 0; mt < 2; mt++) {
            int r0 = mw * 32 + mt * 16 + qr;
            float* base0 = g_pnum + (size_t)bx * (ITILE * 256)
                         + (size_t)r0 * 256 + fw * 64 + 2 * qc;
            float* base1 = base0 + 8 * 256;
            #pragma unroll
            for (int nb = 0; nb < 4; nb++) {
                const float* a = acc + mt * 32 + nb * 8;
                *(float2*)(base0 + nb * 16)     = make_float2(a[0], a[1]);
                *(float2*)(base1 + nb * 16)     = make_float2(a[2], a[3]);
                *(float2*)(base0 + nb * 16 + 8) = make_float2(a[4], a[5]);
                *(float2*)(base1 + nb * 16 + 8) = make_float2(a[6], a[7]);
            }
        }
    }
}

// ---------------------------------------------------------------------------
// Kernel 5: combine splits, normalize, ELU
// ---------------------------------------------------------------------------
__global__ __launch_bounds__(256) void k_comb(float* __restrict__ out) {
    int gid = blockIdx.x * 256 + threadIdx.x;   // float4 index
    int i = gid >> 6;
    int c4 = (gid & 63) * 4;
    int it = i >> 6, row = i & 63;
    size_t b0 = (size_t)it * (ITILE * 256) + (size_t)row * 256 + c4;
    float4 n0 = *(const float4*)(g_pnum + b0);
    float4 n1 = *(const float4*)(g_pnum + b0 + (size_t)128 * (ITILE * 256));
    float z = g_pz[it * ITILE + row] + g_pz[(128 + it) * ITILE + row];
    float inv = 1.f / z;
    float v0 = (n0.x + n1.x) * inv;
    float v1 = (n0.y + n1.y) * inv;
    float v2 = (n0.z + n1.z) * inv;
    float v3 = (n0.w + n1.w) * inv;
    float4 o;
    o.x = (v0 > 0.f) ? v0 : expm1f(v0);
    o.y = (v1 > 0.f) ? v1 : expm1f(v1);
    o.z = (v2 > 0.f) ? v2 : expm1f(v2);
    o.w = (v3 > 0.f) ? v3 : expm1f(v3);
    *(float4*)(out + (size_t)i * FOUT + c4) = o;
}

// ---------------------------------------------------------------------------
extern "C" void kernel_launch(void* const* d_in, const int* in_sizes, int n_in,
                              void* d_out, int out_size) {
    (void)in_sizes; (void)n_in; (void)out_size;
    const float* X   = (const float*)d_in[0];
    const int*   adj = (const int*)d_in[1];
    const float* W   = (const float*)d_in[2];
    const float* a1  = (const float*)d_in[3];
    const float* a2  = (const float*)d_in[4];
    float* out = (float*)d_out;

    cudaFuncSetAttribute(k_attn, cudaFuncAttributeMaxDynamicSharedMemorySize, SMEM_ATTN);

    k_wa<<<FIN / 8, 256>>>(W, a1, a2);
    k_f<<<N / 8, 256>>>(X);
    k_gemm<<<dim3(N / 64, FOUT / 64), 256>>>(X, W);
    k_attn<<<256, 256, SMEM_ATTN>>>(adj);
    k_comb<<<(N * FOUT / 4) / 256, 256>>>(out);
}

// round 15
// speedup vs baseline: 1.0992x; 1.0992x over previous
#include <cuda_runtime.h>
#include <cuda_fp16.h>
#include <cstdint>
#include <cstddef>

#define N    8192
#define FIN  512
#define FOUT 256
#define JT     64                 // j per chunk
#define SPLITS 2
#define JHALF  (N / SPLITS)       // 4096
#define NCHUNK (JHALF / JT)       // 64
#define ITILE  64                 // i rows per CTA

// ---------------- scratch (no cudaMalloc allowed) ----------------
__device__ __half g_hT[FOUT * N];             // 4 MB  h^T fp16  [f][i]
__device__ __half g_Xhi[(size_t)N * FIN];     // 8 MB  X hi fp16 [i][k]
__device__ __half g_Xlo[(size_t)N * FIN];     // 8 MB  X lo fp16
__device__ __half g_WThi[FOUT * FIN];         // 256 KB W^T hi fp16 [f][k]
__device__ __half g_WTlo[FOUT * FIN];         // 256 KB W^T lo fp16
__device__ float  g_Wa1[FIN], g_Wa2[FIN];
__device__ float  g_t[N];                     // f2 * log2(e)
__device__ float  g_u[N];                     // f1 * log2(e)
__device__ int    g_maxbits;                  // max of (t + 64) as fp32 bits
__device__ float  g_pnum[256 * 64 * 256];     // partial numerators (16.8 MB)
__device__ float  g_pz[256 * 64];             // partial Z

#define L2E 1.4426950408889634f

typedef unsigned long long ull;

// ---------------- PTX helpers (baseline sm_80+, legal at .target sm_100) ----
__device__ __forceinline__ uint32_t smem_u32(const void* p) {
    uint32_t a;
    asm("{ .reg .u64 t; cvta.to.shared.u64 t, %1; cvt.u32.u64 %0, t; }" : "=r"(a) : "l"(p));
    return a;
}
#define CP_ASYNC16(dst, src) \
    asm volatile("cp.async.cg.shared.global [%0], [%1], 16;" :: "r"((uint32_t)(dst)), "l"(src) : "memory")
#define CP_COMMIT() asm volatile("cp.async.commit_group;" ::: "memory")
#define CP_WAIT0()  asm volatile("cp.async.wait_group 0;" ::: "memory")

__device__ __forceinline__ void ldsm4(uint32_t* r, uint32_t addr) {
    asm volatile("ldmatrix.sync.aligned.m8n8.x4.shared.b16 {%0,%1,%2,%3}, [%4];"
        : "=r"(r[0]), "=r"(r[1]), "=r"(r[2]), "=r"(r[3]) : "r"(addr));
}
__device__ __forceinline__ void mmaf16(float* d, const uint32_t* a, uint32_t b0, uint32_t b1) {
    asm volatile("mma.sync.aligned.m16n8k16.row.col.f32.f16.f16.f32 "
        "{%0,%1,%2,%3}, {%4,%5,%6,%7}, {%8,%9}, {%0,%1,%2,%3};"
        : "+f"(d[0]), "+f"(d[1]), "+f"(d[2]), "+f"(d[3])
        : "r"(a[0]), "r"(a[1]), "r"(a[2]), "r"(a[3]), "r"(b0), "r"(b1));
}
__device__ __forceinline__ float ex2(float x) {
    float r; asm("ex2.approx.f32 %0, %1;" : "=f"(r) : "f"(x)); return r;
}
__device__ __forceinline__ uint32_t sw128(uint32_t off) { return off ^ ((off >> 3) & 0x70); }

// ---------------------------------------------------------------------------
// Kernel 1: Wa1 = W @ a1, Wa2 = W @ a2 (+ init global max)
// ---------------------------------------------------------------------------
__global__ void k_wa(const float* __restrict__ W,
                     const float* __restrict__ a1,
                     const float* __restrict__ a2) {
    __shared__ float a1s[FOUT], a2s[FOUT];
    int tid = threadIdx.x;
    if (blockIdx.x == 0 && tid == 0) g_maxbits = 0;
    if (tid < FOUT) { a1s[tid] = a1[tid]; a2s[tid] = a2[tid]; }
    __syncthreads();
    int warp = tid >> 5, lane = tid & 31;
    int row = blockIdx.x * 8 + warp;
    const float* wr = W + (size_t)row * FOUT;
    float s1 = 0.f, s2 = 0.f;
    for (int c = lane; c < FOUT; c += 32) {
        float w = wr[c];
        s1 += w * a1s[c];
        s2 += w * a2s[c];
    }
    #pragma unroll
    for (int o = 16; o; o >>= 1) {
        s1 += __shfl_down_sync(0xFFFFFFFFu, s1, o);
        s2 += __shfl_down_sync(0xFFFFFFFFu, s2, o);
    }
    if (lane == 0) { g_Wa1[row] = s1; g_Wa2[row] = s2; }
}

// ---------------------------------------------------------------------------
// Kernel 2: exact fp32 logits f1,f2 -> log2-domain t,u + global max(t)
// ---------------------------------------------------------------------------
__global__ void k_f(const float* __restrict__ X) {
    __shared__ float wa1[FIN], wa2[FIN];
    int tid = threadIdx.x;
    for (int c = tid; c < FIN; c += 256) { wa1[c] = g_Wa1[c]; wa2[c] = g_Wa2[c]; }
    __syncthreads();
    int warp = tid >> 5, lane = tid & 31;
    int row = blockIdx.x * 8 + warp;
    const float* xr = X + (size_t)row * FIN;
    float s1 = 0.f, s2 = 0.f;
    for (int c = lane; c < FIN; c += 32) {
        float x = xr[c];
        s1 += x * wa1[c];
        s2 += x * wa2[c];
    }
    #pragma unroll
    for (int o = 16; o; o >>= 1) {
        s1 += __shfl_down_sync(0xFFFFFFFFu, s1, o);
        s2 += __shfl_down_sync(0xFFFFFFFFu, s2, o);
    }
    if (lane == 0) {
        float t = s2 * L2E;
        g_t[row] = t;
        g_u[row] = s1 * L2E;
        atomicMax(&g_maxbits, __float_as_int(t + 64.f));   // t+64 > 0 always
    }
}

// ---------------------------------------------------------------------------
// Kernel 2b: X -> fp16 hi/lo, [i][k] layout (B operand for k_gemm2)
// grid 4096, 256 threads, 4 floats/thread
// ---------------------------------------------------------------------------
__global__ __launch_bounds__(256) void k_xc(const float* __restrict__ X) {
    int gid = blockIdx.x * 256 + threadIdx.x;
    float4 x = ((const float4*)X)[gid];
    __half h0 = __float2half(x.x), h1 = __float2half(x.y);
    __half h2 = __float2half(x.z), h3 = __float2half(x.w);
    __half2 hhi0 = __halves2half2(h0, h1), hhi1 = __halves2half2(h2, h3);
    __half2 hlo0 = __floats2half2_rn(x.x - __half2float(h0), x.y - __half2float(h1));
    __half2 hlo1 = __floats2half2_rn(x.z - __half2float(h2), x.w - __half2float(h3));
    uint2 vhi = make_uint2(*(uint32_t*)&hhi0, *(uint32_t*)&hhi1);
    uint2 vlo = make_uint2(*(uint32_t*)&hlo0, *(uint32_t*)&hlo1);
    ((uint2*)g_Xhi)[gid] = vhi;
    ((uint2*)g_Xlo)[gid] = vlo;
}

// ---------------------------------------------------------------------------
// Kernel 2c: W -> W^T fp16 hi/lo, [f][k] layout (A operand for k_gemm2)
// grid 512 (k), 256 threads (f)
// ---------------------------------------------------------------------------
__global__ __launch_bounds__(256) void k_wt(const float* __restrict__ W) {
    int k = blockIdx.x, f = threadIdx.x;
    float w = W[(size_t)k * FOUT + f];
    __half hi = __float2half(w);
    __half lo = __float2half(w - __half2float(hi));
    g_WThi[(size_t)f * FIN + k] = hi;
    g_WTlo[(size_t)f * FIN + k] = lo;
}

// ---------------------------------------------------------------------------
// Kernel 3: h^T = W^T @ X^T via fp16 mma.sync, 3 chains (exact to ~2^-22).
// D[m=f 64][n=i 256], K=512 in 8 chunks of 64. Same warp geometry as k_attn.
// grid (FOUT/64, N/256) = (4, 32), 256 threads, single 80KB stage, occ 2.
// ---------------------------------------------------------------------------
#define G_AHI 0
#define G_ALO 8192
#define G_BHI 16384
#define G_BLO 49152
#define SMEM_GEMM 81920

__global__ __launch_bounds__(256, 2) void k_gemm2() {
    extern __shared__ char smem[];
    const uint32_t sb = smem_u32(smem);
    const int tid = threadIdx.x;
    const int f0 = blockIdx.x * 64;
    const int i0 = blockIdx.y * 256;

    const int warp = tid >> 5, lane = tid & 31;
    const int mw = warp >> 2;          // m-warp: f rows [mw*32, mw*32+32)
    const int fw = warp & 3;           // n-warp: i cols [fw*64, fw*64+64)
    const int gr = lane >> 3, lr = lane & 7;
    const int a_rbase = mw * 32 + lr + (gr & 1) * 8;
    const int a_koff = (gr >> 1) * 8;
    const int b_roff = fw * 64 + lr + (gr >> 1) * 8;
    const int b_koff = (gr & 1) * 8;

    float acc[64];
    #pragma unroll
    for (int q = 0; q < 64; q++) acc[q] = 0.f;

    for (int kc = 0; kc < FIN; kc += 64) {
        // ---- fill stage ----
        #pragma unroll
        for (int v = 0; v < 2; v++) {
            int idx = tid * 2 + v;
            int row = idx >> 3, seg = idx & 7;
            uint32_t sw = sw128((uint32_t)(row * 128 + seg * 16));
            const size_t off = (size_t)(f0 + row) * FIN + kc + seg * 8;
            CP_ASYNC16(sb + G_AHI + sw, g_WThi + off);
            CP_ASYNC16(sb + G_ALO + sw, g_WTlo + off);
        }
        {
            const size_t off = (size_t)(i0 + tid) * FIN + kc;
            #pragma unroll
            for (int q = 0; q < 8; q++) {
                uint32_t sw = sw128((uint32_t)(tid * 128 + q * 16));
                CP_ASYNC16(sb + G_BHI + sw, g_Xhi + off + q * 8);
                CP_ASYNC16(sb + G_BLO + sw, g_Xlo + off + q * 8);
            }
        }
        CP_COMMIT();
        CP_WAIT0();
        __syncthreads();
        // ---- MMA: 4 ksteps x 3 chains ----
        #pragma unroll
        for (int k0 = 0; k0 < 64; k0 += 16) {
            uint32_t Ahi0[4], Alo0[4], Ahi1[4], Alo1[4];
            uint32_t ao0 = sw128((uint32_t)(a_rbase * 128 + (k0 + a_koff) * 2));
            uint32_t ao1 = sw128((uint32_t)((a_rbase + 16) * 128 + (k0 + a_koff) * 2));
            ldsm4(Ahi0, sb + G_AHI + ao0);
            ldsm4(Alo0, sb + G_ALO + ao0);
            ldsm4(Ahi1, sb + G_AHI + ao1);
            ldsm4(Alo1, sb + G_ALO + ao1);
            #pragma unroll
            for (int nb = 0; nb < 4; nb++) {
                uint32_t boff = sw128((uint32_t)((b_roff + nb * 16) * 128 + (k0 + b_koff) * 2));
                uint32_t Bh[4], Bl[4];
                ldsm4(Bh, sb + G_BHI + boff);
                ldsm4(Bl, sb + G_BLO + boff);
                float* d00 = acc + nb * 8;
                float* d01 = acc + nb * 8 + 4;
                float* d10 = acc + 32 + nb * 8;
                float* d11 = acc + 32 + nb * 8 + 4;
                mmaf16(d00, Ahi0, Bh[0], Bh[1]);
                mmaf16(d01, Ahi0, Bh[2], Bh[3]);
                mmaf16(d10, Ahi1, Bh[0], Bh[1]);
                mmaf16(d11, Ahi1, Bh[2], Bh[3]);
                mmaf16(d00, Ahi0, Bl[0], Bl[1]);
                mmaf16(d01, Ahi0, Bl[2], Bl[3]);
                mmaf16(d10, Ahi1, Bl[0], Bl[1]);
                mmaf16(d11, Ahi1, Bl[2], Bl[3]);
                mmaf16(d00, Alo0, Bh[0], Bh[1]);
                mmaf16(d01, Alo0, Bh[2], Bh[3]);
                mmaf16(d10, Alo1, Bh[0], Bh[1]);
                mmaf16(d11, Alo1, Bh[2], Bh[3]);
            }
        }
        __syncthreads();
    }

    // ---- epilogue: fp32 acc -> fp16 h^T[f][i] (aligned half2 stores) ----
    {
        const int qr = lane >> 2, qc = lane & 3;
        #pragma unroll
        for (int mt = 0; mt < 2; mt++) {
            int fr = f0 + mw * 32 + mt * 16 + qr;
            #pragma unroll
            for (int nb = 0; nb < 4; nb++) {
                const float* a = acc + mt * 32 + nb * 8;
                int col = i0 + fw * 64 + nb * 16 + 2 * qc;
                __half2 v0 = __floats2half2_rn(a[0], a[1]);
                __half2 v1 = __floats2half2_rn(a[2], a[3]);
                __half2 v2 = __floats2half2_rn(a[4], a[5]);
                __half2 v3 = __floats2half2_rn(a[6], a[7]);
                *(__half2*)(g_hT + (size_t)fr * N + col)           = v0;
                *(__half2*)(g_hT + (size_t)(fr + 8) * N + col)     = v1;
                *(__half2*)(g_hT + (size_t)fr * N + col + 8)       = v2;
                *(__half2*)(g_hT + (size_t)(fr + 8) * N + col + 8) = v3;
            }
        }
    }
}

// ---------------------------------------------------------------------------
// Kernel 4: masked-softmax aggregation via fp16 mma.sync, SINGLE chain.
// (unchanged from R13/R14 best: log-domain gen, double buffer, occ 2)
// ---------------------------------------------------------------------------
#define STAGE 40960
#define OFF_A(s) ((s) * STAGE)
#define OFF_B(s) ((s) * STAGE + 8192)
#define SMEM_ATTN (2 * STAGE)   // 81920

__global__ __launch_bounds__(256, 2) void k_attn(const int* __restrict__ adj) {
    extern __shared__ char smem[];
    const uint32_t sb = smem_u32(smem);
    const int tid = threadIdx.x;
    const int bx = blockIdx.x;
    const int i_tile = bx & 127, split = bx >> 7;
    const int i0 = i_tile * ITILE;
    const int jbase = split * JHALF;

    const int warp = tid >> 5, lane = tid & 31;
    const int mw = warp >> 2;
    const int fw = warp & 3;
    const int gr = lane >> 3, lr = lane & 7;
    const int a_rbase = mw * 32 + lr + (gr & 1) * 8;
    const int a_koff = (gr >> 1) * 8;
    const int b_roff = fw * 64 + lr + (gr >> 1) * 8;
    const int b_koff = (gr & 1) * 8;

    const int il = tid >> 2;
    const int jb = (tid & 3) * 16;
    const float u = g_u[i0 + il];
    float kk;
    {
        float T = __int_as_float(g_maxbits) - 64.f;
        float smax = u + T;
        float b = (smax >= 0.f) ? smax : 0.2f * smax;
        kk = 13.f - floorf(b);
    }
    const int* adjrow = adj + (size_t)(i0 + il) * N;
    float zacc = 0.f;

    float acc[64];
    #pragma unroll
    for (int q = 0; q < 64; q++) acc[q] = 0.f;

    auto fillB = [&](int s, int jglob) {
        const __half* src = g_hT + (size_t)tid * N + jglob;
        #pragma unroll
        for (int q = 0; q < 8; q++) {
            uint32_t sw = sw128(tid * 128 + q * 16);
            CP_ASYNC16(sb + OFF_B(s) + sw, src + q * 8);
        }
    };
    auto genA = [&](int s, const int4* am4, int jglob) {
        const int* am = (const int*)am4;
        const float4* tp = (const float4*)(g_t + jglob + jb);
        float tv[16];
        #pragma unroll
        for (int q = 0; q < 4; q++) {
            float4 t4 = tp[q];
            tv[q * 4 + 0] = t4.x;
            tv[q * 4 + 1] = t4.y;
            tv[q * 4 + 2] = t4.z;
            tv[q * 4 + 3] = t4.w;
        }
        uint32_t phv[8];
        #pragma unroll
        for (int p = 0; p < 8; p++) {
            float w[2];
            #pragma unroll
            for (int e = 0; e < 2; e++) {
                int jj = p * 2 + e;
                float s_ = tv[jj] + u;
                float ee = (s_ >= 0.f) ? s_ : 0.2f * s_;
                float wv = ex2(ee + kk);
                w[e] = am[jj] ? wv : 0.f;
            }
            __half2 hh = __floats2half2_rn(w[0], w[1]);
            zacc += __low2float(hh) + __high2float(hh);
            phv[p] = *(uint32_t*)&hh;
        }
        uint32_t sw0 = sw128((uint32_t)(il * 128 + jb * 2));
        uint32_t sw1 = sw128((uint32_t)(il * 128 + jb * 2 + 16));
        *(uint4*)(smem + OFF_A(s) + sw0) = make_uint4(phv[0], phv[1], phv[2], phv[3]);
        *(uint4*)(smem + OFF_A(s) + sw1) = make_uint4(phv[4], phv[5], phv[6], phv[7]);
    };

    {
        int4 aR[4];
        const int4* ap = (const int4*)(adjrow + jbase + jb);
        aR[0] = ap[0]; aR[1] = ap[1]; aR[2] = ap[2]; aR[3] = ap[3];
        fillB(0, jbase);
        CP_COMMIT();
        genA(0, aR, jbase);
        CP_WAIT0();
        __syncthreads();
    }

    for (int c = 0; c < NCHUNK; c++) {
        const int s = c & 1;
        const bool more = (c + 1 < NCHUNK);
        int4 aR[4];
        int jn = jbase + (c + 1) * JT;
        if (more) {
            const int4* ap = (const int4*)(adjrow + jn + jb);
            aR[0] = ap[0]; aR[1] = ap[1]; aR[2] = ap[2]; aR[3] = ap[3];
            fillB(s ^ 1, jn);
            CP_COMMIT();
        }
        #pragma unroll
        for (int k0 = 0; k0 < JT; k0 += 16) {
            uint32_t A0[4], A1[4], B[4][4];
            uint32_t ao0 = sw128((uint32_t)(a_rbase * 128 + (k0 + a_koff) * 2));
            uint32_t ao1 = sw128((uint32_t)((a_rbase + 16) * 128 + (k0 + a_koff) * 2));
            ldsm4(A0, sb + OFF_A(s) + ao0);
            ldsm4(A1, sb + OFF_A(s) + ao1);
            #pragma unroll
            for (int nb = 0; nb < 4; nb++) {
                uint32_t boff = sw128((uint32_t)((b_roff + nb * 16) * 128 + (k0 + b_koff) * 2));
                ldsm4(B[nb], sb + OFF_B(s) + boff);
            }
            #pragma unroll
            for (int nb = 0; nb < 4; nb++) {
                mmaf16(acc + nb * 8,          A0, B[nb][0], B[nb][1]);
                mmaf16(acc + nb * 8 + 4,      A0, B[nb][2], B[nb][3]);
                mmaf16(acc + 32 + nb * 8,     A1, B[nb][0], B[nb][1]);
                mmaf16(acc + 32 + nb * 8 + 4, A1, B[nb][2], B[nb][3]);
            }
        }
        if (more) {
            genA(s ^ 1, aR, jn);
            CP_WAIT0();
        }
        __syncthreads();
    }

    zacc += __shfl_xor_sync(0xFFFFFFFFu, zacc, 1);
    zacc += __shfl_xor_sync(0xFFFFFFFFu, zacc, 2);
    if ((tid & 3) == 0) g_pz[bx * ITILE + il] = zacc;

    {
        const int qr = lane >> 2, qc = lane & 3;
        #pragma unroll
        for (int mt = 0; mt < 2; mt++) {
            int r0 = mw * 32 + mt * 16 + qr;
            float* base0 = g_pnum + (size_t)bx * (ITILE * 256)
                         + (size_t)r0 * 256 + fw * 64 + 2 * qc;
            float* base1 = base0 + 8 * 256;
            #pragma unroll
            for (int nb = 0; nb < 4; nb++) {
                const float* a = acc + mt * 32 + nb * 8;
                *(float2*)(base0 + nb * 16)     = make_float2(a[0], a[1]);
                *(float2*)(base1 + nb * 16)     = make_float2(a[2], a[3]);
                *(float2*)(base0 + nb * 16 + 8) = make_float2(a[4], a[5]);
                *(float2*)(base1 + nb * 16 + 8) = make_float2(a[6], a[7]);
            }
        }
    }
}

// ---------------------------------------------------------------------------
// Kernel 5: combine splits, normalize, ELU
// ---------------------------------------------------------------------------
__global__ __launch_bounds__(256) void k_comb(float* __restrict__ out) {
    int gid = blockIdx.x * 256 + threadIdx.x;
    int i = gid >> 6;
    int c4 = (gid & 63) * 4;
    int it = i >> 6, row = i & 63;
    size_t b0 = (size_t)it * (ITILE * 256) + (size_t)row * 256 + c4;
    float4 n0 = *(const float4*)(g_pnum + b0);
    float4 n1 = *(const float4*)(g_pnum + b0 + (size_t)128 * (ITILE * 256));
    float z = g_pz[it * ITILE + row] + g_pz[(128 + it) * ITILE + row];
    float inv = 1.f / z;
    float v0 = (n0.x + n1.x) * inv;
    float v1 = (n0.y + n1.y) * inv;
    float v2 = (n0.z + n1.z) * inv;
    float v3 = (n0.w + n1.w) * inv;
    float4 o;
    o.x = (v0 > 0.f) ? v0 : expm1f(v0);
    o.y = (v1 > 0.f) ? v1 : expm1f(v1);
    o.z = (v2 > 0.f) ? v2 : expm1f(v2);
    o.w = (v3 > 0.f) ? v3 : expm1f(v3);
    *(float4*)(out + (size_t)i * FOUT + c4) = o;
}

// ---------------------------------------------------------------------------
extern "C" void kernel_launch(void* const* d_in, const int* in_sizes, int n_in,
                              void* d_out, int out_size) {
    (void)in_sizes; (void)n_in; (void)out_size;
    const float* X   = (const float*)d_in[0];
    const int*   adj = (const int*)d_in[1];
    const float* W   = (const float*)d_in[2];
    const float* a1  = (const float*)d_in[3];
    const float* a2  = (const float*)d_in[4];
    float* out = (float*)d_out;

    cudaFuncSetAttribute(k_attn, cudaFuncAttributeMaxDynamicSharedMemorySize, SMEM_ATTN);
    cudaFuncSetAttribute(k_gemm2, cudaFuncAttributeMaxDynamicSharedMemorySize, SMEM_GEMM);

    k_wa<<<FIN / 8, 256>>>(W, a1, a2);
    k_f<<<N / 8, 256>>>(X);
    k_xc<<<(N * FIN / 4) / 256, 256>>>(X);
    k_wt<<<FIN, FOUT>>>(W);
    k_gemm2<<<dim3(FOUT / 64, N / 256), 256, SMEM_GEMM>>>();
    k_attn<<<256, 256, SMEM_ATTN>>>(adj);
    k_comb<<<(N * FOUT / 4) / 256, 256>>>(out);
}